// round 11
// baseline (speedup 1.0000x reference)
#include <cuda_runtime.h>
#include <cuda_fp16.h>
#include <stdint.h>

// Hopfield layer via warp-level fp16 mma.sync (sm_100 target, no tcgen05).
// R11: 2 CTAs/SM (QT=128, 8 warps x 16 rows, __launch_bounds__(256,2)) ->
// 4 warps/SMSP for latency hiding + all 148 SMs active. fp16 operands,
// fp32 accum, KV tile in two 32-key halves, cp.async double-buffered KV,
// unnormalized softmax (bounded scores), normalize at end.

#define DM 512
#define QT 128
#define ST 64
#define THREADS 256

// dynamic smem: 2 KV buffers (8KB each) + Q tile (16KB) = 32KB
#define KBUF(i)  ((uint32_t)(i) * 8192u)
#define QB0 16384
#define SMEM_TOTAL 32768

#define NELEM (2u * 2048u * 512u)
__device__ __half gYh[NELEM];
__device__ __half gRh[NELEM];
__device__ __half gTh[NELEM];

static __device__ __forceinline__ uint32_t s2u(const void* p) {
    uint32_t a;
    asm("{ .reg .u64 t; cvta.to.shared.u64 t, %1; cvt.u32.u64 %0, t; }"
        : "=r"(a) : "l"(p));
    return a;
}
static __device__ __forceinline__ uint32_t off(int row, int chunk) {
    return (uint32_t)(row * 128 + ((chunk ^ (row & 7)) << 4));
}
static __device__ __forceinline__ float ex2f_(float x) {
    float r; asm("ex2.approx.ftz.f32 %0, %1;" : "=f"(r) : "f"(x)); return r;
}
static __device__ __forceinline__ uint32_t packh(float x, float y) {
    __half hx = __float2half_rn(x), hy = __float2half_rn(y);
    return ((uint32_t)__half_as_ushort(hy) << 16) | (uint32_t)__half_as_ushort(hx);
}

static __device__ __forceinline__ void mma_f16(float c[4], const uint32_t a[4],
                                               const uint32_t b[2]) {
    asm volatile(
        "mma.sync.aligned.m16n8k16.row.col.f32.f16.f16.f32 "
        "{%0,%1,%2,%3}, {%4,%5,%6,%7}, {%8,%9}, {%0,%1,%2,%3};"
        : "+f"(c[0]), "+f"(c[1]), "+f"(c[2]), "+f"(c[3])
        : "r"(a[0]), "r"(a[1]), "r"(a[2]), "r"(a[3]), "r"(b[0]), "r"(b[1]));
}
#define LDSM4(r, a) \
    asm volatile("ldmatrix.sync.aligned.m8n8.x4.shared.b16 {%0,%1,%2,%3}, [%4];" \
        : "=r"((r)[0]), "=r"((r)[1]), "=r"((r)[2]), "=r"((r)[3]) : "r"(a))
#define LDSM4T(r, a) \
    asm volatile("ldmatrix.sync.aligned.m8n8.x4.trans.shared.b16 {%0,%1,%2,%3}, [%4];" \
        : "=r"((r)[0]), "=r"((r)[1]), "=r"((r)[2]), "=r"((r)[3]) : "r"(a))
#define CPA(dst, src) \
    asm volatile("cp.async.cg.shared.global [%0], [%1], 16;" :: "r"(dst), "l"(src))
#define CPC() asm volatile("cp.async.commit_group;" ::: "memory")
#define CPW(n) asm volatile("cp.async.wait_group %0;" :: "n"(n) : "memory")

__global__ void tohalf(const float4* __restrict__ src, uint2* __restrict__ dst, int n4)
{
    int i = blockIdx.x * blockDim.x + threadIdx.x;
    if (i < n4) {
        float4 x = src[i];
        dst[i] = make_uint2(packh(x.x, x.y), packh(x.z, x.w));
    }
}

__global__ __launch_bounds__(THREADS, 2)
void hopfield_mma(const __half* __restrict__ Qm, const __half* __restrict__ Km,
                  float* __restrict__ outF, __half* __restrict__ outH,
                  int L, int S)
{
    extern __shared__ __align__(16) uint8_t smem[];
    const uint32_t sb = s2u(smem);
    const uint32_t qB = sb + QB0;

    const int tid = threadIdx.x;
    const int wid = tid >> 5;
    const int lane = tid & 31;
    const int h = blockIdx.y, b = blockIdx.z;
    const float C = 0.125f * 1.4426950408889634f;

    // ---- stage Q tile (128 rows x 64 halves = 16KB) ----
    const __half* qg = Qm + ((size_t)b * L + (size_t)blockIdx.x * QT) * DM + h * 64;
    {
        int c = tid & 7, r0 = tid >> 3;   // 0..31
#pragma unroll
        for (int i = 0; i < 4; i++) {
            int row = r0 + i * 32;        // 0..127
            CPA(qB + off(row, c), (const char*)(qg + (size_t)row * DM) + c * 16);
        }
        CPC(); CPW(0);
    }
    __syncthreads();

    // per-warp A fragment: 16x64; warp w owns rows 16w..16w+15
    uint32_t qf[4][4];
    {
        int gr = 16 * wid + (lane & 15);
#pragma unroll
        for (int t = 0; t < 4; t++) {
            int ch = 2 * t + (lane >> 4);
            LDSM4(qf[t], qB + off(gr, ch));
        }
    }

    float oacc[8][4];
#pragma unroll
    for (int j = 0; j < 8; j++)
#pragma unroll
        for (int i = 0; i < 4; i++) oacc[j][i] = 0.f;
    float l0 = 0.f, l1 = 0.f;

    const __half* kg = Km + (size_t)b * S * DM + h * 64;
    const int NT = S / ST;   // 32

    // prefetch tiles 0, 1
    {
        int c = tid & 7, r0 = tid >> 3;
#pragma unroll
        for (int pf = 0; pf < 2; pf++) {
            uint32_t bh = sb + KBUF(pf);
            const char* hs = (const char*)(kg + (size_t)pf * ST * DM);
#pragma unroll
            for (int i = 0; i < 2; i++) {
                int row = r0 + i * 32;
                CPA(bh + off(row, c), hs + (size_t)row * DM * 2 + c * 16);
            }
            CPC();
        }
    }

    for (int t = 0; t < NT; t++) {
        CPW(1);
        __syncthreads();
        const uint32_t kb = sb + KBUF(t & 1);

        // ---- process tile in two 32-key halves (bounds live registers) ----
#pragma unroll
        for (int half = 0; half < 2; half++) {
            // GEMM1-half: sc[4 n-blocks][4] = Q x K^T
            float sc[4][4];
#pragma unroll
            for (int j = 0; j < 4; j++)
#pragma unroll
                for (int i = 0; i < 4; i++) sc[j][i] = 0.f;

#pragma unroll
            for (int j = 0; j < 4; j++) {
                int row = 32 * half + 8 * j + (lane & 7);
                uint32_t bh[8];
                LDSM4(bh + 0, kb + off(row, (lane >> 3)));
                LDSM4(bh + 4, kb + off(row, 4 + (lane >> 3)));
#pragma unroll
                for (int t4 = 0; t4 < 4; t4++)
                    mma_f16(sc[j], qf[t4], bh + 2 * t4);
            }

            // softmax-half (unnormalized), pack P to fp16 A-fragments
            uint32_t ph[2][4];
#pragma unroll
            for (int kt = 0; kt < 2; kt++) {
                float e0 = ex2f_(sc[2 * kt][0] * C),     e1 = ex2f_(sc[2 * kt][1] * C);
                float e2 = ex2f_(sc[2 * kt][2] * C),     e3 = ex2f_(sc[2 * kt][3] * C);
                float e4 = ex2f_(sc[2 * kt + 1][0] * C), e5 = ex2f_(sc[2 * kt + 1][1] * C);
                float e6 = ex2f_(sc[2 * kt + 1][2] * C), e7 = ex2f_(sc[2 * kt + 1][3] * C);
                l0 += (e0 + e1) + (e4 + e5);
                l1 += (e2 + e3) + (e6 + e7);
                ph[kt][0] = packh(e0, e1);
                ph[kt][1] = packh(e2, e3);
                ph[kt][2] = packh(e4, e5);
                ph[kt][3] = packh(e6, e7);
            }

            // GEMM2-half: O += P x V (V == K tile, .trans)
#pragma unroll
            for (int kt = 0; kt < 2; kt++) {
                int row = 32 * half + 16 * kt + (lane & 7) + (lane & 8);
#pragma unroll
                for (int jp = 0; jp < 4; jp++) {
                    int ch = 2 * jp + (lane >> 4);
                    uint32_t vh[4];
                    LDSM4T(vh, kb + off(row, ch));
                    mma_f16(oacc[2 * jp],     ph[kt], vh + 0);
                    mma_f16(oacc[2 * jp + 1], ph[kt], vh + 2);
                }
            }
        }
        __syncthreads();

        // prefetch tile t+2 into the buffer just freed
        if (t + 2 < NT) {
            int c = tid & 7, r0 = tid >> 3;
            const char* hs = (const char*)(kg + (size_t)(t + 2) * ST * DM);
#pragma unroll
            for (int i = 0; i < 2; i++) {
                int row = r0 + i * 32;
                CPA(kb + off(row, c), hs + (size_t)row * DM * 2 + c * 16);
            }
        }
        CPC();
    }

    // ---- normalize + store ----
    l0 += __shfl_xor_sync(0xffffffffu, l0, 1);
    l0 += __shfl_xor_sync(0xffffffffu, l0, 2);
    l1 += __shfl_xor_sync(0xffffffffu, l1, 1);
    l1 += __shfl_xor_sync(0xffffffffu, l1, 2);
    float inv0 = 1.f / l0, inv1 = 1.f / l1;

    const int r = lane >> 2, cb = (lane & 3) * 2;
    size_t base = ((size_t)b * L + (size_t)blockIdx.x * QT + 16 * wid) * DM + h * 64;
    if (outF) {
#pragma unroll
        for (int j = 0; j < 8; j++) {
            *(float2*)(outF + base + (size_t)r * DM + 8 * j + cb) =
                make_float2(oacc[j][0] * inv0, oacc[j][1] * inv0);
            *(float2*)(outF + base + (size_t)(r + 8) * DM + 8 * j + cb) =
                make_float2(oacc[j][2] * inv1, oacc[j][3] * inv1);
        }
    } else {
#pragma unroll
        for (int j = 0; j < 8; j++) {
            *(uint32_t*)(outH + base + (size_t)r * DM + 8 * j + cb) =
                packh(oacc[j][0] * inv0, oacc[j][1] * inv0);
            *(uint32_t*)(outH + base + (size_t)(r + 8) * DM + 8 * j + cb) =
                packh(oacc[j][2] * inv1, oacc[j][3] * inv1);
        }
    }
}

extern "C" void kernel_launch(void* const* d_in, const int* in_sizes, int n_in,
                              void* d_out, int out_size)
{
    const float* R = (const float*)d_in[0];
    const float* Y = (const float*)d_in[1];
    float* out = (float*)d_out;

    const int B = 2, H = 8;
    const int L = in_sizes[0] / (B * DM);   // 2048
    const int S = in_sizes[1] / (B * DM);   // 2048

    __half *Yh, *Rh, *Th;
    cudaGetSymbolAddress((void**)&Yh, gYh);
    cudaGetSymbolAddress((void**)&Rh, gRh);
    cudaGetSymbolAddress((void**)&Th, gTh);

    cudaFuncSetAttribute(hopfield_mma, cudaFuncAttributeMaxDynamicSharedMemorySize,
                         SMEM_TOTAL);

    const int n4 = (int)(NELEM / 4);
    tohalf<<<(n4 + 255) / 256, 256>>>((const float4*)Y, (uint2*)Yh, n4);
    tohalf<<<(n4 + 255) / 256, 256>>>((const float4*)R, (uint2*)Rh, n4);

    dim3 grid(L / QT, H, B);
    dim3 block(THREADS);
    // step 1: Q=R -> fp16 tmp
    hopfield_mma<<<grid, block, SMEM_TOTAL>>>(Rh, Yh, nullptr, Th, L, S);
    // step 2: Q=tmp -> fp32 out
    hopfield_mma<<<grid, block, SMEM_TOTAL>>>(Th, Yh, out, nullptr, L, S);
}

// round 12
// speedup vs baseline: 1.1105x; 1.1105x over previous
#include <cuda_runtime.h>
#include <cuda_fp16.h>
#include <stdint.h>

// Hopfield layer via warp-level fp16 mma.sync (sm_100 target, no tcgen05).
// R12: R10 (QT=256, 8 warps x 32 rows, fp16 single-term) + two independent
// 4-warp groups with private KV double-buffers and named barriers -> group
// desync lets one group's MMAs cover the other's softmax/LDSM phases.
// fp32 accum, unnormalized softmax (bounded scores), normalize at end.

#define DM 512
#define QT 256
#define ST 64
#define THREADS 256

// dynamic smem: per-group KV double buffers (2 x 8KB x 2 groups) + Q (32KB)
#define GRPSTRIDE 16384u
#define QB0 32768
#define SMEM_TOTAL 65536

#define NELEM (2u * 2048u * 512u)
__device__ __half gYh[NELEM];
__device__ __half gRh[NELEM];
__device__ __half gTh[NELEM];

static __device__ __forceinline__ uint32_t s2u(const void* p) {
    uint32_t a;
    asm("{ .reg .u64 t; cvta.to.shared.u64 t, %1; cvt.u32.u64 %0, t; }"
        : "=r"(a) : "l"(p));
    return a;
}
static __device__ __forceinline__ uint32_t off(int row, int chunk) {
    return (uint32_t)(row * 128 + ((chunk ^ (row & 7)) << 4));
}
static __device__ __forceinline__ float ex2f_(float x) {
    float r; asm("ex2.approx.ftz.f32 %0, %1;" : "=f"(r) : "f"(x)); return r;
}
static __device__ __forceinline__ uint32_t packh(float x, float y) {
    __half hx = __float2half_rn(x), hy = __float2half_rn(y);
    return ((uint32_t)__half_as_ushort(hy) << 16) | (uint32_t)__half_as_ushort(hx);
}

static __device__ __forceinline__ void mma_f16(float c[4], const uint32_t a[4],
                                               const uint32_t b[2]) {
    asm volatile(
        "mma.sync.aligned.m16n8k16.row.col.f32.f16.f16.f32 "
        "{%0,%1,%2,%3}, {%4,%5,%6,%7}, {%8,%9}, {%0,%1,%2,%3};"
        : "+f"(c[0]), "+f"(c[1]), "+f"(c[2]), "+f"(c[3])
        : "r"(a[0]), "r"(a[1]), "r"(a[2]), "r"(a[3]), "r"(b[0]), "r"(b[1]));
}
#define LDSM4(r, a) \
    asm volatile("ldmatrix.sync.aligned.m8n8.x4.shared.b16 {%0,%1,%2,%3}, [%4];" \
        : "=r"((r)[0]), "=r"((r)[1]), "=r"((r)[2]), "=r"((r)[3]) : "r"(a))
#define LDSM4T(r, a) \
    asm volatile("ldmatrix.sync.aligned.m8n8.x4.trans.shared.b16 {%0,%1,%2,%3}, [%4];" \
        : "=r"((r)[0]), "=r"((r)[1]), "=r"((r)[2]), "=r"((r)[3]) : "r"(a))
#define CPA(dst, src) \
    asm volatile("cp.async.cg.shared.global [%0], [%1], 16;" :: "r"(dst), "l"(src))
#define CPC() asm volatile("cp.async.commit_group;" ::: "memory")
#define CPW(n) asm volatile("cp.async.wait_group %0;" :: "n"(n) : "memory")
#define BARG(id) asm volatile("bar.sync %0, 128;" :: "r"(id) : "memory")

__global__ void tohalf(const float4* __restrict__ src, uint2* __restrict__ dst, int n4)
{
    int i = blockIdx.x * blockDim.x + threadIdx.x;
    if (i < n4) {
        float4 x = src[i];
        dst[i] = make_uint2(packh(x.x, x.y), packh(x.z, x.w));
    }
}

// fetch one 64-row fp16 tile (8KB) with 128 group threads
static __device__ __forceinline__ void fetch_tile(uint32_t buf, const __half* src,
                                                  int gtid) {
    int c = gtid & 7, r0 = gtid >> 3;   // 0..15
#pragma unroll
    for (int i = 0; i < 4; i++) {
        int row = r0 + 16 * i;
        CPA(buf + off(row, c), (const char*)(src + (size_t)row * DM) + c * 16);
    }
}

__global__ __launch_bounds__(THREADS, 1)
void hopfield_mma(const __half* __restrict__ Qm, const __half* __restrict__ Km,
                  float* __restrict__ outF, __half* __restrict__ outH,
                  int L, int S)
{
    extern __shared__ __align__(16) uint8_t smem[];
    const uint32_t sb = s2u(smem);
    const uint32_t qB = sb + QB0;

    const int tid = threadIdx.x;
    const int wid = tid >> 5;
    const int lane = tid & 31;
    const int g = wid >> 2;          // group 0 or 1
    const int gtid = tid & 127;
    const int barid = 1 + g;
    const int h = blockIdx.y, b = blockIdx.z;
    const float C = 0.125f * 1.4426950408889634f;

    const uint32_t gb = sb + (uint32_t)g * GRPSTRIDE;
    const uint32_t kbuf[2] = { gb, gb + 8192u };

    // ---- stage full Q tile (256 rows x 64 halves = 32KB), all 256 threads ----
    const __half* qg = Qm + ((size_t)b * L + (size_t)blockIdx.x * QT) * DM + h * 64;
    {
        int c = tid & 7, r0 = tid >> 3;   // 0..31
#pragma unroll
        for (int i = 0; i < 8; i++) {
            int row = r0 + i * 32;        // 0..255
            CPA(qB + off(row, c), (const char*)(qg + (size_t)row * DM) + c * 16);
        }
        CPC(); CPW(0);
    }
    __syncthreads();

    // per-warp A fragments: 2 row-tiles of 16x64; warp w owns rows 32w..32w+31
    uint32_t qf[2][4][4];
#pragma unroll
    for (int rt = 0; rt < 2; rt++) {
        int gr = 32 * wid + 16 * rt + (lane & 15);
#pragma unroll
        for (int t = 0; t < 4; t++) {
            int ch = 2 * t + (lane >> 4);
            LDSM4(qf[rt][t], qB + off(gr, ch));
        }
    }

    float oacc[2][8][4];
#pragma unroll
    for (int rt = 0; rt < 2; rt++)
#pragma unroll
        for (int j = 0; j < 8; j++)
#pragma unroll
            for (int i = 0; i < 4; i++) oacc[rt][j][i] = 0.f;
    float lsum[2][2] = {{0.f, 0.f}, {0.f, 0.f}};

    const __half* kg = Km + (size_t)b * S * DM + h * 64;
    const int NT = S / ST;   // 32

    // per-group prefetch tiles 0, 1
    fetch_tile(kbuf[0], kg, gtid);                      CPC();
    fetch_tile(kbuf[1], kg + (size_t)ST * DM, gtid);    CPC();

    for (int t = 0; t < NT; t++) {
        CPW(1);
        BARG(barid);
        const uint32_t kb = kbuf[t & 1];

        // ---- process tile in two 32-key halves (bounds live registers) ----
#pragma unroll
        for (int half = 0; half < 2; half++) {
            // GEMM1-half: sc[rt][4 n-blocks][4] = Q x K^T
            float sc[2][4][4];
#pragma unroll
            for (int rt = 0; rt < 2; rt++)
#pragma unroll
                for (int j = 0; j < 4; j++)
#pragma unroll
                    for (int i = 0; i < 4; i++) sc[rt][j][i] = 0.f;

#pragma unroll
            for (int j = 0; j < 4; j++) {
                int row = 32 * half + 8 * j + (lane & 7);
                uint32_t bh[8];
                LDSM4(bh + 0, kb + off(row, (lane >> 3)));
                LDSM4(bh + 4, kb + off(row, 4 + (lane >> 3)));
#pragma unroll
                for (int t4 = 0; t4 < 4; t4++)
#pragma unroll
                    for (int rt = 0; rt < 2; rt++)
                        mma_f16(sc[rt][j], qf[rt][t4], bh + 2 * t4);
            }

            // softmax-half (unnormalized), pack P to fp16 A-fragments
            uint32_t ph[2][2][4];
#pragma unroll
            for (int rt = 0; rt < 2; rt++) {
#pragma unroll
                for (int kt = 0; kt < 2; kt++) {
                    float e0 = ex2f_(sc[rt][2 * kt][0] * C),     e1 = ex2f_(sc[rt][2 * kt][1] * C);
                    float e2 = ex2f_(sc[rt][2 * kt][2] * C),     e3 = ex2f_(sc[rt][2 * kt][3] * C);
                    float e4 = ex2f_(sc[rt][2 * kt + 1][0] * C), e5 = ex2f_(sc[rt][2 * kt + 1][1] * C);
                    float e6 = ex2f_(sc[rt][2 * kt + 1][2] * C), e7 = ex2f_(sc[rt][2 * kt + 1][3] * C);
                    lsum[rt][0] += (e0 + e1) + (e4 + e5);
                    lsum[rt][1] += (e2 + e3) + (e6 + e7);
                    ph[rt][kt][0] = packh(e0, e1);
                    ph[rt][kt][1] = packh(e2, e3);
                    ph[rt][kt][2] = packh(e4, e5);
                    ph[rt][kt][3] = packh(e6, e7);
                }
            }

            // GEMM2-half: O += P x V (V == K tile, .trans; V frags shared over rt)
#pragma unroll
            for (int kt = 0; kt < 2; kt++) {
                int row = 32 * half + 16 * kt + (lane & 7) + (lane & 8);
#pragma unroll
                for (int jp = 0; jp < 4; jp++) {
                    int ch = 2 * jp + (lane >> 4);
                    uint32_t vh[4];
                    LDSM4T(vh, kb + off(row, ch));
#pragma unroll
                    for (int rt = 0; rt < 2; rt++) {
                        mma_f16(oacc[rt][2 * jp],     ph[rt][kt], vh + 0);
                        mma_f16(oacc[rt][2 * jp + 1], ph[rt][kt], vh + 2);
                    }
                }
            }
        }
        BARG(barid);

        // prefetch tile t+2 into the buffer just freed (group-local)
        if (t + 2 < NT)
            fetch_tile(kb, kg + (size_t)(t + 2) * ST * DM, gtid);
        CPC();
    }

    // ---- normalize + store ----
    const int r = lane >> 2, cb = (lane & 3) * 2;
#pragma unroll
    for (int rt = 0; rt < 2; rt++) {
        float l0 = lsum[rt][0], l1 = lsum[rt][1];
        l0 += __shfl_xor_sync(0xffffffffu, l0, 1);
        l0 += __shfl_xor_sync(0xffffffffu, l0, 2);
        l1 += __shfl_xor_sync(0xffffffffu, l1, 1);
        l1 += __shfl_xor_sync(0xffffffffu, l1, 2);
        float inv0 = 1.f / l0, inv1 = 1.f / l1;

        size_t base = ((size_t)b * L + (size_t)blockIdx.x * QT + 32 * wid + 16 * rt) * DM
                    + h * 64;
        if (outF) {
#pragma unroll
            for (int j = 0; j < 8; j++) {
                *(float2*)(outF + base + (size_t)r * DM + 8 * j + cb) =
                    make_float2(oacc[rt][j][0] * inv0, oacc[rt][j][1] * inv0);
                *(float2*)(outF + base + (size_t)(r + 8) * DM + 8 * j + cb) =
                    make_float2(oacc[rt][j][2] * inv1, oacc[rt][j][3] * inv1);
            }
        } else {
#pragma unroll
            for (int j = 0; j < 8; j++) {
                *(uint32_t*)(outH + base + (size_t)r * DM + 8 * j + cb) =
                    packh(oacc[rt][j][0] * inv0, oacc[rt][j][1] * inv0);
                *(uint32_t*)(outH + base + (size_t)(r + 8) * DM + 8 * j + cb) =
                    packh(oacc[rt][j][2] * inv1, oacc[rt][j][3] * inv1);
            }
        }
    }
}

extern "C" void kernel_launch(void* const* d_in, const int* in_sizes, int n_in,
                              void* d_out, int out_size)
{
    const float* R = (const float*)d_in[0];
    const float* Y = (const float*)d_in[1];
    float* out = (float*)d_out;

    const int B = 2, H = 8;
    const int L = in_sizes[0] / (B * DM);   // 2048
    const int S = in_sizes[1] / (B * DM);   // 2048

    __half *Yh, *Rh, *Th;
    cudaGetSymbolAddress((void**)&Yh, gYh);
    cudaGetSymbolAddress((void**)&Rh, gRh);
    cudaGetSymbolAddress((void**)&Th, gTh);

    cudaFuncSetAttribute(hopfield_mma, cudaFuncAttributeMaxDynamicSharedMemorySize,
                         SMEM_TOTAL);

    const int n4 = (int)(NELEM / 4);
    tohalf<<<(n4 + 255) / 256, 256>>>((const float4*)Y, (uint2*)Yh, n4);
    tohalf<<<(n4 + 255) / 256, 256>>>((const float4*)R, (uint2*)Rh, n4);

    dim3 grid(L / QT, H, B);
    dim3 block(THREADS);
    // step 1: Q=R -> fp16 tmp
    hopfield_mma<<<grid, block, SMEM_TOTAL>>>(Rh, Yh, nullptr, Th, L, S);
    // step 2: Q=tmp -> fp32 out
    hopfield_mma<<<grid, block, SMEM_TOTAL>>>(Th, Yh, out, nullptr, L, S);
}

// round 13
// speedup vs baseline: 1.2130x; 1.0923x over previous
#include <cuda_runtime.h>
#include <cuda_fp16.h>
#include <stdint.h>

// Hopfield layer via warp-level fp16 mma.sync (sm_100 target, no tcgen05).
// R13: R10 base (QT=256, 8 warps x 32 rows, fp16 single-term, half-split KV
// tiles) with the softmax instruction stream cut ~3x:
//   - softmax scale C folded into Q at conversion (no per-score FMUL)
//   - P packed via cvt.rn.f16x2.f32 (1 instr per pair)
//   - row-sums l computed by an extra ones-column MMA (fp32, no shuffles)
// fp32 accum, unnormalized softmax (bounded scores), normalize at end.

#define DM 512
#define QT 256
#define ST 64
#define THREADS 256

// dynamic smem: 2 KV buffers (8KB each) + Q tile (32KB)
#define KBUF(i)  ((uint32_t)(i) * 8192u)
#define QB0 16384
#define SMEM_TOTAL 49152

#define NELEM (2u * 2048u * 512u)
__device__ __half gYh[NELEM];
__device__ __half gRh[NELEM];
__device__ __half gTh[NELEM];

static __device__ __forceinline__ uint32_t s2u(const void* p) {
    uint32_t a;
    asm("{ .reg .u64 t; cvta.to.shared.u64 t, %1; cvt.u32.u64 %0, t; }"
        : "=r"(a) : "l"(p));
    return a;
}
static __device__ __forceinline__ uint32_t off(int row, int chunk) {
    return (uint32_t)(row * 128 + ((chunk ^ (row & 7)) << 4));
}
static __device__ __forceinline__ float ex2f_(float x) {
    float r; asm("ex2.approx.ftz.f32 %0, %1;" : "=f"(r) : "f"(x)); return r;
}
// pack two fp32 into fp16x2 (lo -> low half) in one instruction
static __device__ __forceinline__ uint32_t packh2(float lo, float hi) {
    uint32_t r;
    asm("cvt.rn.f16x2.f32 %0, %1, %2;" : "=r"(r) : "f"(hi), "f"(lo));
    return r;
}

static __device__ __forceinline__ void mma_f16(float c[4], const uint32_t a[4],
                                               const uint32_t b[2]) {
    asm volatile(
        "mma.sync.aligned.m16n8k16.row.col.f32.f16.f16.f32 "
        "{%0,%1,%2,%3}, {%4,%5,%6,%7}, {%8,%9}, {%0,%1,%2,%3};"
        : "+f"(c[0]), "+f"(c[1]), "+f"(c[2]), "+f"(c[3])
        : "r"(a[0]), "r"(a[1]), "r"(a[2]), "r"(a[3]), "r"(b[0]), "r"(b[1]));
}
#define LDSM4(r, a) \
    asm volatile("ldmatrix.sync.aligned.m8n8.x4.shared.b16 {%0,%1,%2,%3}, [%4];" \
        : "=r"((r)[0]), "=r"((r)[1]), "=r"((r)[2]), "=r"((r)[3]) : "r"(a))
#define LDSM4T(r, a) \
    asm volatile("ldmatrix.sync.aligned.m8n8.x4.trans.shared.b16 {%0,%1,%2,%3}, [%4];" \
        : "=r"((r)[0]), "=r"((r)[1]), "=r"((r)[2]), "=r"((r)[3]) : "r"(a))
#define CPA(dst, src) \
    asm volatile("cp.async.cg.shared.global [%0], [%1], 16;" :: "r"(dst), "l"(src))
#define CPC() asm volatile("cp.async.commit_group;" ::: "memory")
#define CPW(n) asm volatile("cp.async.wait_group %0;" :: "n"(n) : "memory")

// fp32 -> fp16 convert with optional scale (packed pairs)
__global__ void tohalf(const float4* __restrict__ src, uint2* __restrict__ dst,
                       int n4, float scale)
{
    int i = blockIdx.x * blockDim.x + threadIdx.x;
    if (i < n4) {
        float4 x = src[i];
        dst[i] = make_uint2(packh2(x.x * scale, x.y * scale),
                            packh2(x.z * scale, x.w * scale));
    }
}

__global__ __launch_bounds__(THREADS, 1)
void hopfield_mma(const __half* __restrict__ Qm, const __half* __restrict__ Km,
                  float* __restrict__ outF, __half* __restrict__ outH,
                  int L, int S, float outScale)
{
    extern __shared__ __align__(16) uint8_t smem[];
    const uint32_t sb = s2u(smem);
    const uint32_t qB = sb + QB0;

    const int tid = threadIdx.x;
    const int wid = tid >> 5;
    const int lane = tid & 31;
    const int h = blockIdx.y, b = blockIdx.z;

    const uint32_t ones2[2] = { 0x3C003C00u, 0x3C003C00u };   // fp16 {1,1}

    // ---- stage full Q tile (256 rows x 64 halves = 32KB) ----
    const __half* qg = Qm + ((size_t)b * L + (size_t)blockIdx.x * QT) * DM + h * 64;
    {
        int c = tid & 7, r0 = tid >> 3;   // 0..31
#pragma unroll
        for (int i = 0; i < 8; i++) {
            int row = r0 + i * 32;        // 0..255
            CPA(qB + off(row, c), (const char*)(qg + (size_t)row * DM) + c * 16);
        }
        CPC(); CPW(0);
    }
    __syncthreads();

    // per-warp A fragments: 2 row-tiles of 16x64; warp w owns rows 32w..32w+31
    uint32_t qf[2][4][4];
#pragma unroll
    for (int rt = 0; rt < 2; rt++) {
        int gr = 32 * wid + 16 * rt + (lane & 15);
#pragma unroll
        for (int t = 0; t < 4; t++) {
            int ch = 2 * t + (lane >> 4);
            LDSM4(qf[rt][t], qB + off(gr, ch));
        }
    }

    float oacc[2][8][4];
#pragma unroll
    for (int rt = 0; rt < 2; rt++)
#pragma unroll
        for (int j = 0; j < 8; j++)
#pragma unroll
            for (int i = 0; i < 4; i++) oacc[rt][j][i] = 0.f;
    float lacc[2][4] = {{0.f, 0.f, 0.f, 0.f}, {0.f, 0.f, 0.f, 0.f}};

    const __half* kg = Km + (size_t)b * S * DM + h * 64;
    const int NT = S / ST;   // 32

    // prefetch tiles 0, 1
    {
        int c = tid & 7, r0 = tid >> 3;
#pragma unroll
        for (int pf = 0; pf < 2; pf++) {
            uint32_t bh = sb + KBUF(pf);
            const char* hs = (const char*)(kg + (size_t)pf * ST * DM);
#pragma unroll
            for (int i = 0; i < 2; i++) {
                int row = r0 + i * 32;
                CPA(bh + off(row, c), hs + (size_t)row * DM * 2 + c * 16);
            }
            CPC();
        }
    }

    for (int t = 0; t < NT; t++) {
        CPW(1);
        __syncthreads();
        const uint32_t kb = sb + KBUF(t & 1);

        // ---- process tile in two 32-key halves (bounds live registers) ----
#pragma unroll
        for (int half = 0; half < 2; half++) {
            // GEMM1-half: sc[rt][4 n-blocks][4] = Qscaled x K^T  (scores * C)
            float sc[2][4][4];
#pragma unroll
            for (int rt = 0; rt < 2; rt++)
#pragma unroll
                for (int j = 0; j < 4; j++)
#pragma unroll
                    for (int i = 0; i < 4; i++) sc[rt][j][i] = 0.f;

#pragma unroll
            for (int j = 0; j < 4; j++) {
                int row = 32 * half + 8 * j + (lane & 7);
                uint32_t bh[8];
                LDSM4(bh + 0, kb + off(row, (lane >> 3)));
                LDSM4(bh + 4, kb + off(row, 4 + (lane >> 3)));
#pragma unroll
                for (int t4 = 0; t4 < 4; t4++)
#pragma unroll
                    for (int rt = 0; rt < 2; rt++)
                        mma_f16(sc[rt][j], qf[rt][t4], bh + 2 * t4);
            }

            // softmax-half: p = exp2(sc) (scale pre-folded), pack via f16x2 cvt
            uint32_t ph[2][2][4];
#pragma unroll
            for (int rt = 0; rt < 2; rt++) {
#pragma unroll
                for (int kt = 0; kt < 2; kt++) {
                    ph[rt][kt][0] = packh2(ex2f_(sc[rt][2 * kt][0]),
                                           ex2f_(sc[rt][2 * kt][1]));
                    ph[rt][kt][1] = packh2(ex2f_(sc[rt][2 * kt][2]),
                                           ex2f_(sc[rt][2 * kt][3]));
                    ph[rt][kt][2] = packh2(ex2f_(sc[rt][2 * kt + 1][0]),
                                           ex2f_(sc[rt][2 * kt + 1][1]));
                    ph[rt][kt][3] = packh2(ex2f_(sc[rt][2 * kt + 1][2]),
                                           ex2f_(sc[rt][2 * kt + 1][3]));
                }
            }

            // GEMM2-half: O += P x V, plus l += P x ones (row sums in fp32)
#pragma unroll
            for (int kt = 0; kt < 2; kt++) {
                int row = 32 * half + 16 * kt + (lane & 7) + (lane & 8);
#pragma unroll
                for (int jp = 0; jp < 4; jp++) {
                    int ch = 2 * jp + (lane >> 4);
                    uint32_t vh[4];
                    LDSM4T(vh, kb + off(row, ch));
#pragma unroll
                    for (int rt = 0; rt < 2; rt++) {
                        mma_f16(oacc[rt][2 * jp],     ph[rt][kt], vh + 0);
                        mma_f16(oacc[rt][2 * jp + 1], ph[rt][kt], vh + 2);
                    }
                }
#pragma unroll
                for (int rt = 0; rt < 2; rt++)
                    mma_f16(lacc[rt], ph[rt][kt], ones2);
            }
        }
        __syncthreads();

        // prefetch tile t+2 into the buffer just freed
        if (t + 2 < NT) {
            int c = tid & 7, r0 = tid >> 3;
            const char* hs = (const char*)(kg + (size_t)(t + 2) * ST * DM);
#pragma unroll
            for (int i = 0; i < 2; i++) {
                int row = r0 + i * 32;
                CPA(kb + off(row, c), hs + (size_t)row * DM * 2 + c * 16);
            }
        }
        CPC();
    }

    // ---- normalize + store (lacc cols all equal the row sum; no shuffles) ----
    const int r = lane >> 2, cb = (lane & 3) * 2;
#pragma unroll
    for (int rt = 0; rt < 2; rt++) {
        float inv0 = outScale / lacc[rt][0];
        float inv1 = outScale / lacc[rt][2];

        size_t base = ((size_t)b * L + (size_t)blockIdx.x * QT + 32 * wid + 16 * rt) * DM
                    + h * 64;
        if (outF) {
#pragma unroll
            for (int j = 0; j < 8; j++) {
                *(float2*)(outF + base + (size_t)r * DM + 8 * j + cb) =
                    make_float2(oacc[rt][j][0] * inv0, oacc[rt][j][1] * inv0);
                *(float2*)(outF + base + (size_t)(r + 8) * DM + 8 * j + cb) =
                    make_float2(oacc[rt][j][2] * inv1, oacc[rt][j][3] * inv1);
            }
        } else {
#pragma unroll
            for (int j = 0; j < 8; j++) {
                *(uint32_t*)(outH + base + (size_t)r * DM + 8 * j + cb) =
                    packh2(oacc[rt][j][0] * inv0, oacc[rt][j][1] * inv0);
                *(uint32_t*)(outH + base + (size_t)(r + 8) * DM + 8 * j + cb) =
                    packh2(oacc[rt][j][2] * inv1, oacc[rt][j][3] * inv1);
            }
        }
    }
}

extern "C" void kernel_launch(void* const* d_in, const int* in_sizes, int n_in,
                              void* d_out, int out_size)
{
    const float* R = (const float*)d_in[0];
    const float* Y = (const float*)d_in[1];
    float* out = (float*)d_out;

    const int B = 2, H = 8;
    const int L = in_sizes[0] / (B * DM);   // 2048
    const int S = in_sizes[1] / (B * DM);   // 2048
    const float C = 0.125f * 1.4426950408889634f;   // scale * log2(e)

    __half *Yh, *Rh, *Th;
    cudaGetSymbolAddress((void**)&Yh, gYh);
    cudaGetSymbolAddress((void**)&Rh, gRh);
    cudaGetSymbolAddress((void**)&Th, gTh);

    cudaFuncSetAttribute(hopfield_mma, cudaFuncAttributeMaxDynamicSharedMemorySize,
                         SMEM_TOTAL);

    const int n4 = (int)(NELEM / 4);
    // K/V operand unscaled; Q operand carries the softmax scale (in log2 base)
    tohalf<<<(n4 + 255) / 256, 256>>>((const float4*)Y, (uint2*)Yh, n4, 1.0f);
    tohalf<<<(n4 + 255) / 256, 256>>>((const float4*)R, (uint2*)Rh, n4, C);

    dim3 grid(L / QT, H, B);
    dim3 block(THREADS);
    // step 1: Q=R*C -> fp16 tmp, scale C folded into tmp (it is step-2's Q)
    hopfield_mma<<<grid, block, SMEM_TOTAL>>>(Rh, Yh, nullptr, Th, L, S, C);
    // step 2: Q=tmp -> fp32 out, plain normalization
    hopfield_mma<<<grid, block, SMEM_TOTAL>>>(Th, Yh, out, nullptr, L, S, 1.0f);
}